// round 4
// baseline (speedup 1.0000x reference)
#include <cuda_runtime.h>

#define BATCH 128
#define DIMZ  128
#define NELEM 3072
#define MPAD  4096
#define NCH   32
#define CW    96    // NCH*CW == NELEM
#define TS    97    // emd smem row stride (odd -> conflict-free)
#define ZS    129   // zsim smem row stride (odd -> conflict-free)

// ---------------- scratch (static device globals; no allocation) -----------
__device__ float g_xs[BATCH * NELEM];         // sorted rows of x
__device__ float g_zcos[BATCH * BATCH];       // cosine similarity matrix
__device__ int   g_maxbits;                   // float-as-int max of g_zcos
                                              // (replay-safe: same max every call)
__device__ float g_part[NCH * BATCH * BATCH]; // split-K EMD partials
__device__ float g_bsum[16];                  // per-block mse sums
__device__ unsigned g_cnt;                    // last-block counter (self-resetting)

// ---------------- fused norm + cosine + max --------------------------------
// grid 128, block 128, dyn smem = (128*ZS + 128) floats.
// Every block loads all of z coalesced, computes all inv-norms locally
// (redundant but free), then its own cosine row i from smem.
extern __shared__ float zs_dyn[];
__global__ void k_zsim(const float* __restrict__ z) {
    float* zs   = zs_dyn;             // [128][ZS]
    float* sinv = zs_dyn + BATCH * ZS; // [128]
    __shared__ float redm[4];
    int i = blockIdx.x, t = threadIdx.x;

    for (int idx = t; idx < BATCH * DIMZ; idx += DIMZ) {
        int r = idx >> 7, c = idx & 127;
        zs[r * ZS + c] = z[idx];
    }
    __syncthreads();

    // inv-norm of row t (banks (t+kk)%32 -> conflict-free)
    {
        const float* zr = zs + t * ZS;
        float s0 = 0.f, s1 = 0.f, s2 = 0.f, s3 = 0.f;
        #pragma unroll
        for (int kk = 0; kk < DIMZ; kk += 4) {
            float v0 = zr[kk], v1 = zr[kk + 1], v2 = zr[kk + 2], v3 = zr[kk + 3];
            s0 += v0 * v0; s1 += v1 * v1; s2 += v2 * v2; s3 += v3 * v3;
        }
        float s = (s0 + s1) + (s2 + s3);
        sinv[t] = 1.f / fmaxf(sqrtf(s), 1e-12f);
    }
    __syncthreads();

    // cosine(i, t)
    const float* za = zs + i * ZS;   // broadcast across lanes
    const float* zb = zs + t * ZS;   // conflict-free across lanes
    float d0 = 0.f, d1 = 0.f, d2 = 0.f, d3 = 0.f;
    #pragma unroll
    for (int kk = 0; kk < DIMZ; kk += 4) {
        d0 += za[kk]     * zb[kk];
        d1 += za[kk + 1] * zb[kk + 1];
        d2 += za[kk + 2] * zb[kk + 2];
        d3 += za[kk + 3] * zb[kk + 3];
    }
    float c = ((d0 + d1) + (d2 + d3)) * sinv[i] * sinv[t];
    g_zcos[i * BATCH + t] = c;

    // block max -> global atomic max (row contains diag 1.0 -> max > 0,
    // so positive-float int ordering is monotonic)
    float m = c;
    #pragma unroll
    for (int o = 16; o; o >>= 1) m = fmaxf(m, __shfl_xor_sync(0xffffffffu, m, o));
    if ((t & 31) == 0) redm[t >> 5] = m;
    __syncthreads();
    if (t == 0) {
        float mx = fmaxf(fmaxf(redm[0], redm[1]), fmaxf(redm[2], redm[3]));
        atomicMax(&g_maxbits, __float_as_int(mx));
    }
}

// ---------------- hybrid bitonic sort --------------------------------------
__device__ __forceinline__ void cswap(float& a, float& b, bool asc) {
    float lo = fminf(a, b), hi = fmaxf(a, b);
    a = asc ? lo : hi;
    b = asc ? hi : lo;
}

__device__ __forceinline__ void reg_sweep(float v[4], int e0, int k, int jstart) {
    bool asc = ((e0 & k) == 0);
    for (int j = jstart; j >= 4; j >>= 1) {
        bool low = ((e0 & j) == 0);
        bool km = (low == asc);
        #pragma unroll
        for (int r = 0; r < 4; r++) {
            float o = __shfl_xor_sync(0xffffffffu, v[r], j >> 2);
            v[r] = km ? fminf(v[r], o) : fmaxf(v[r], o);
        }
    }
    if (jstart >= 2) {
        cswap(v[0], v[2], asc);
        cswap(v[1], v[3], asc);
    }
    {
        bool a0 = ((e0 & k) == 0);
        bool a1 = (((e0 + 2) & k) == 0);
        cswap(v[0], v[1], a0);
        cswap(v[2], v[3], a1);
    }
}

__global__ __launch_bounds__(1024, 1) void k_sort(const float* __restrict__ x) {
    __shared__ __align__(16) float s[MPAD];
    int t = threadIdx.x;
    int row = blockIdx.x;
    int e0 = t * 4;

    float v[4];
    if (e0 < NELEM) {
        float4 f = *reinterpret_cast<const float4*>(x + row * NELEM + e0);
        v[0] = f.x; v[1] = f.y; v[2] = f.z; v[3] = f.w;
    } else {
        v[0] = v[1] = v[2] = v[3] = __int_as_float(0x7f800000);
    }

    for (int k = 2; k <= 128; k <<= 1)
        reg_sweep(v, e0, k, k >> 1);

    *reinterpret_cast<float4*>(&s[e0]) = make_float4(v[0], v[1], v[2], v[3]);
    __syncthreads();

    for (int k = 256; k <= MPAD; k <<= 1) {
        for (int j = k >> 1; j >= 128; j >>= 1) {
            #pragma unroll
            for (int mm = 0; mm < 2; mm++) {
                int m = t + (mm << 10);
                int i = ((m & ~(j - 1)) << 1) | (m & (j - 1));
                int l = i | j;
                bool asc = ((i & k) == 0);
                float a = s[i], b = s[l];
                float lo = fminf(a, b), hi = fmaxf(a, b);
                s[i] = asc ? lo : hi;
                s[l] = asc ? hi : lo;
            }
            __syncthreads();
        }
        float4 f = *reinterpret_cast<const float4*>(&s[e0]);
        v[0] = f.x; v[1] = f.y; v[2] = f.z; v[3] = f.w;
        reg_sweep(v, e0, k, 64);
        if (k < MPAD) {
            *reinterpret_cast<float4*>(&s[e0]) = make_float4(v[0], v[1], v[2], v[3]);
            __syncthreads();
        }
    }

    if (e0 < NELEM)
        *reinterpret_cast<float4*>(g_xs + row * NELEM + e0) =
            make_float4(v[0], v[1], v[2], v[3]);
}

// ---------------- split-K EMD ----------------------------------------------
// grid (2,2,NCH) = 128 blocks, 256 threads, 4x4 outputs/thread.
extern __shared__ float sm_emd[];
__global__ __launch_bounds__(256, 1) void k_emd() {
    float* sa = sm_emd;
    float* sb = sm_emd + 64 * TS;
    int tid = threadIdx.x;
    int w = tid >> 5, l = tid & 31;
    int tx = (l & 7) | ((w & 1) << 3);
    int ty = (l >> 3) | ((w >> 1) << 2);
    int i0 = blockIdx.y * 64, j0 = blockIdx.x * 64, c0 = blockIdx.z * CW;

    for (int idx = tid; idx < 64 * CW; idx += 256) {
        int r = idx / CW, c = idx - r * CW;
        sa[r * TS + c] = g_xs[(i0 + r) * NELEM + c0 + c];
        sb[r * TS + c] = g_xs[(j0 + r) * NELEM + c0 + c];
    }
    __syncthreads();

    float acc[16];
    #pragma unroll
    for (int q = 0; q < 16; q++) acc[q] = 0.f;

    const float* pa = sa + (ty * 4) * TS;
    const float* pb = sb + (tx * 4) * TS;
    #pragma unroll 4
    for (int c = 0; c < CW; c++) {
        float a[4], b[4];
        #pragma unroll
        for (int r = 0; r < 4; r++) a[r] = pa[r * TS + c];
        #pragma unroll
        for (int r = 0; r < 4; r++) b[r] = pb[r * TS + c];
        #pragma unroll
        for (int r = 0; r < 4; r++)
            #pragma unroll
            for (int q = 0; q < 4; q++) {
                float d = __fmaf_rn(b[q], -1.f, a[r]);
                acc[r * 4 + q] = __fmaf_rn(fabsf(d), 1.f, acc[r * 4 + q]);
            }
    }

    float* out = g_part + blockIdx.z * (BATCH * BATCH);
    int ri = i0 + ty * 4, rj = j0 + tx * 4;
    #pragma unroll
    for (int r = 0; r < 4; r++)
        #pragma unroll
        for (int q = 0; q < 4; q++)
            out[(ri + r) * BATCH + rj + q] = acc[r * 4 + q];
}

// ---------------- fused combine + MSE + final (last-block) -----------------
// grid 16, block 256, 4 consecutive idx per thread via float4.
__global__ void k_mse(float* __restrict__ out) {
    __shared__ float red[8];
    __shared__ bool last;
    int t = threadIdx.x;
    int base4 = blockIdx.x * 256 + t;            // float4 index

    float4 s = make_float4(0.f, 0.f, 0.f, 0.f);
    #pragma unroll
    for (int ch = 0; ch < NCH; ch++) {
        float4 p = reinterpret_cast<const float4*>(g_part)[ch * (BATCH * BATCH / 4) + base4];
        s.x += p.x; s.y += p.y; s.z += p.z; s.w += p.w;
    }
    float4 zc = reinterpret_cast<const float4*>(g_zcos)[base4];
    float gmax = __int_as_float(g_maxbits);
    const float inv = 1.f / (float)NELEM;
    float dx = s.x * inv + zc.x - gmax;
    float dy = s.y * inv + zc.y - gmax;
    float dz = s.z * inv + zc.z - gmax;
    float dw = s.w * inv + zc.w - gmax;
    float v = dx * dx + dy * dy + dz * dz + dw * dw;

    #pragma unroll
    for (int o = 16; o; o >>= 1) v += __shfl_xor_sync(0xffffffffu, v, o);
    if ((t & 31) == 0) red[t >> 5] = v;
    __syncthreads();
    if (t == 0) {
        float bs = 0.f;
        #pragma unroll
        for (int q = 0; q < 8; q++) bs += red[q];
        g_bsum[blockIdx.x] = bs;
        __threadfence();
        unsigned c = atomicAdd(&g_cnt, 1u);
        last = (c == 15u);
    }
    __syncthreads();
    if (last && t < 16) {
        float w = g_bsum[t];
        #pragma unroll
        for (int o = 8; o; o >>= 1) w += __shfl_xor_sync(0x0000ffffu, w, o);
        if (t == 0) {
            out[0] = w * (1.f / (float)(BATCH * BATCH));
            g_cnt = 0u;  // self-reset for next graph replay
        }
    }
}

// ---------------- launch ----------------------------------------------------
extern "C" void kernel_launch(void* const* d_in, const int* in_sizes, int n_in,
                              void* d_out, int out_size) {
    const float* z = (const float*)d_in[0];
    const float* x = (const float*)d_in[1];
    if (n_in >= 2 && in_sizes[0] == BATCH * NELEM) {  // defensive swap
        const float* tmp = z; z = x; x = tmp;
    }

    int smem_emd  = 2 * 64 * TS * (int)sizeof(float);          // 49664 B
    int smem_zsim = (BATCH * ZS + BATCH) * (int)sizeof(float); // 66560 B
    static int attr_set = 0;
    if (!attr_set) {
        cudaFuncSetAttribute(k_emd,  cudaFuncAttributeMaxDynamicSharedMemorySize, smem_emd);
        cudaFuncSetAttribute(k_zsim, cudaFuncAttributeMaxDynamicSharedMemorySize, smem_zsim);
        attr_set = 1;
    }

    k_zsim<<<BATCH, DIMZ, smem_zsim>>>(z);
    k_sort<<<BATCH, 1024>>>(x);
    dim3 ge(2, 2, NCH);
    k_emd<<<ge, 256, smem_emd>>>();
    k_mse<<<16, 256>>>((float*)d_out);
}

// round 5
// speedup vs baseline: 1.1220x; 1.1220x over previous
#include <cuda_runtime.h>

#define BATCH 128
#define DIMZ  128
#define NELEM 3072
#define MPAD  4096
#define NCH   32
#define CW    96    // NCH*CW == NELEM
#define TS    97    // emd smem row stride (odd -> conflict-free)
#define ZS    129   // zsim smem row stride (odd -> conflict-free)
#define MSEB  128   // k_mse grid size

// ---------------- scratch (static device globals; no allocation) -----------
__device__ float g_xs[BATCH * NELEM];         // sorted rows of x
__device__ float g_zcos[BATCH * BATCH];       // cosine similarity matrix
__device__ int   g_maxbits;                   // float-as-int max of g_zcos
                                              // (replay-safe: same max every call)
__device__ float g_part[NCH * BATCH * BATCH]; // split-K EMD partials
__device__ float g_bsum[MSEB];                // per-block mse sums
__device__ unsigned g_cnt;                    // last-block counter (self-resetting)

// ---------------- fused norm + cosine + max --------------------------------
extern __shared__ float zs_dyn[];
__global__ void k_zsim(const float* __restrict__ z) {
    float* zs   = zs_dyn;              // [128][ZS]
    float* sinv = zs_dyn + BATCH * ZS; // [128]
    __shared__ float redm[4];
    int i = blockIdx.x, t = threadIdx.x;

    for (int idx = t; idx < BATCH * DIMZ; idx += DIMZ) {
        int r = idx >> 7, c = idx & 127;
        zs[r * ZS + c] = z[idx];
    }
    __syncthreads();

    {
        const float* zr = zs + t * ZS;
        float s0 = 0.f, s1 = 0.f, s2 = 0.f, s3 = 0.f;
        #pragma unroll
        for (int kk = 0; kk < DIMZ; kk += 4) {
            float v0 = zr[kk], v1 = zr[kk + 1], v2 = zr[kk + 2], v3 = zr[kk + 3];
            s0 += v0 * v0; s1 += v1 * v1; s2 += v2 * v2; s3 += v3 * v3;
        }
        float s = (s0 + s1) + (s2 + s3);
        sinv[t] = 1.f / fmaxf(sqrtf(s), 1e-12f);
    }
    __syncthreads();

    const float* za = zs + i * ZS;   // broadcast
    const float* zb = zs + t * ZS;   // conflict-free
    float d0 = 0.f, d1 = 0.f, d2 = 0.f, d3 = 0.f;
    #pragma unroll
    for (int kk = 0; kk < DIMZ; kk += 4) {
        d0 += za[kk]     * zb[kk];
        d1 += za[kk + 1] * zb[kk + 1];
        d2 += za[kk + 2] * zb[kk + 2];
        d3 += za[kk + 3] * zb[kk + 3];
    }
    float c = ((d0 + d1) + (d2 + d3)) * sinv[i] * sinv[t];
    g_zcos[i * BATCH + t] = c;

    float m = c;
    #pragma unroll
    for (int o = 16; o; o >>= 1) m = fmaxf(m, __shfl_xor_sync(0xffffffffu, m, o));
    if ((t & 31) == 0) redm[t >> 5] = m;
    __syncthreads();
    if (t == 0) {
        float mx = fmaxf(fmaxf(redm[0], redm[1]), fmaxf(redm[2], redm[3]));
        atomicMax(&g_maxbits, __float_as_int(mx));  // max >= 1 > 0: int-order monotonic
    }
}

// ---------------- hybrid bitonic sort --------------------------------------
__device__ __forceinline__ void cswap(float& a, float& b, bool asc) {
    float lo = fminf(a, b), hi = fmaxf(a, b);
    a = asc ? lo : hi;
    b = asc ? hi : lo;
}

__device__ __forceinline__ void reg_sweep(float v[4], int e0, int k, int jstart) {
    bool asc = ((e0 & k) == 0);
    for (int j = jstart; j >= 4; j >>= 1) {
        bool low = ((e0 & j) == 0);
        bool km = (low == asc);
        #pragma unroll
        for (int r = 0; r < 4; r++) {
            float o = __shfl_xor_sync(0xffffffffu, v[r], j >> 2);
            v[r] = km ? fminf(v[r], o) : fmaxf(v[r], o);
        }
    }
    if (jstart >= 2) {
        cswap(v[0], v[2], asc);
        cswap(v[1], v[3], asc);
    }
    {
        bool a0 = ((e0 & k) == 0);
        bool a1 = (((e0 + 2) & k) == 0);
        cswap(v[0], v[1], a0);
        cswap(v[2], v[3], a1);
    }
}

__global__ __launch_bounds__(1024, 1) void k_sort(const float* __restrict__ x) {
    __shared__ __align__(16) float s[MPAD];
    int t = threadIdx.x;
    int row = blockIdx.x;
    int e0 = t * 4;

    float v[4];
    if (e0 < NELEM) {
        float4 f = *reinterpret_cast<const float4*>(x + row * NELEM + e0);
        v[0] = f.x; v[1] = f.y; v[2] = f.z; v[3] = f.w;
    } else {
        v[0] = v[1] = v[2] = v[3] = __int_as_float(0x7f800000);
    }

    for (int k = 2; k <= 128; k <<= 1)
        reg_sweep(v, e0, k, k >> 1);

    *reinterpret_cast<float4*>(&s[e0]) = make_float4(v[0], v[1], v[2], v[3]);
    __syncthreads();

    for (int k = 256; k <= MPAD; k <<= 1) {
        for (int j = k >> 1; j >= 128; j >>= 1) {
            #pragma unroll
            for (int mm = 0; mm < 2; mm++) {
                int m = t + (mm << 10);
                int i = ((m & ~(j - 1)) << 1) | (m & (j - 1));
                int l = i | j;
                bool asc = ((i & k) == 0);
                float a = s[i], b = s[l];
                float lo = fminf(a, b), hi = fmaxf(a, b);
                s[i] = asc ? lo : hi;
                s[l] = asc ? hi : lo;
            }
            __syncthreads();
        }
        float4 f = *reinterpret_cast<const float4*>(&s[e0]);
        v[0] = f.x; v[1] = f.y; v[2] = f.z; v[3] = f.w;
        reg_sweep(v, e0, k, 64);
        if (k < MPAD) {
            *reinterpret_cast<float4*>(&s[e0]) = make_float4(v[0], v[1], v[2], v[3]);
            __syncthreads();
        }
    }

    if (e0 < NELEM)
        *reinterpret_cast<float4*>(g_xs + row * NELEM + e0) =
            make_float4(v[0], v[1], v[2], v[3]);
}

// ---------------- split-K EMD ----------------------------------------------
// grid (2,2,NCH) = 128 blocks, 256 threads, 4x4 outputs/thread.
extern __shared__ float sm_emd[];
__global__ __launch_bounds__(256, 1) void k_emd() {
    float* sa = sm_emd;
    float* sb = sm_emd + 64 * TS;
    int tid = threadIdx.x;
    int w = tid >> 5, l = tid & 31;
    int tx = (l & 7) | ((w & 1) << 3);
    int ty = (l >> 3) | ((w >> 1) << 2);
    int i0 = blockIdx.y * 64, j0 = blockIdx.x * 64, c0 = blockIdx.z * CW;

    for (int idx = tid; idx < 64 * CW; idx += 256) {
        int r = idx / CW, c = idx - r * CW;
        sa[r * TS + c] = g_xs[(i0 + r) * NELEM + c0 + c];
        sb[r * TS + c] = g_xs[(j0 + r) * NELEM + c0 + c];
    }
    __syncthreads();

    float acc[16];
    #pragma unroll
    for (int q = 0; q < 16; q++) acc[q] = 0.f;

    const float* pa = sa + (ty * 4) * TS;
    const float* pb = sb + (tx * 4) * TS;
    #pragma unroll 4
    for (int c = 0; c < CW; c++) {
        float a[4], b[4];
        #pragma unroll
        for (int r = 0; r < 4; r++) a[r] = pa[r * TS + c];
        #pragma unroll
        for (int r = 0; r < 4; r++) b[r] = pb[r * TS + c];
        #pragma unroll
        for (int r = 0; r < 4; r++)
            #pragma unroll
            for (int q = 0; q < 4; q++) {
                float d = __fmaf_rn(b[q], -1.f, a[r]);                     // FFMA-imm
                acc[r * 4 + q] = __fmaf_rn(fabsf(d), 1.f, acc[r * 4 + q]); // FFMA-imm
            }
    }

    float* out = g_part + blockIdx.z * (BATCH * BATCH);
    int ri = i0 + ty * 4, rj = j0 + tx * 4;
    #pragma unroll
    for (int r = 0; r < 4; r++)
        *reinterpret_cast<float4*>(out + (ri + r) * BATCH + rj) =
            make_float4(acc[r * 4 + 0], acc[r * 4 + 1], acc[r * 4 + 2], acc[r * 4 + 3]);
}

// ---------------- fused combine + MSE + final (last-block) -----------------
// grid MSEB=128, block 256. Block b covers 32 float4-indices; warp w sums
// chunk group w (4 chunks). Cross-warp combine in smem, fixed-tree finish.
__global__ void k_mse(float* __restrict__ out) {
    __shared__ float4 sm[8][32];
    __shared__ float red2[4];
    __shared__ bool last;
    int t = threadIdx.x;
    int lane = t & 31, w = t >> 5;
    int I = blockIdx.x * 32 + lane;          // float4 index into [BATCH*BATCH/4]

    const float4* p4 = reinterpret_cast<const float4*>(g_part);
    float4 s = make_float4(0.f, 0.f, 0.f, 0.f);
    #pragma unroll
    for (int q = 0; q < 4; q++) {
        float4 p = p4[(w * 4 + q) * (BATCH * BATCH / 4) + I];
        s.x += p.x; s.y += p.y; s.z += p.z; s.w += p.w;
    }
    sm[w][lane] = s;
    __syncthreads();

    float v = 0.f;
    if (w == 0) {
        float4 a = sm[0][lane];
        #pragma unroll
        for (int g = 1; g < 8; g++) {
            float4 b = sm[g][lane];
            a.x += b.x; a.y += b.y; a.z += b.z; a.w += b.w;
        }
        float4 zc = reinterpret_cast<const float4*>(g_zcos)[I];
        float gmax = __int_as_float(g_maxbits);
        const float inv = 1.f / (float)NELEM;
        float dx = a.x * inv + zc.x - gmax;
        float dy = a.y * inv + zc.y - gmax;
        float dz = a.z * inv + zc.z - gmax;
        float dw = a.w * inv + zc.w - gmax;
        v = dx * dx + dy * dy + dz * dz + dw * dw;
        #pragma unroll
        for (int o = 16; o; o >>= 1) v += __shfl_xor_sync(0xffffffffu, v, o);
    }
    if (t == 0) {
        g_bsum[blockIdx.x] = v;
        __threadfence();
        unsigned c = atomicAdd(&g_cnt, 1u);
        last = (c == (unsigned)(MSEB - 1));
    }
    __syncthreads();
    if (last) {
        if (t < MSEB) {
            float wv = g_bsum[t];
            #pragma unroll
            for (int o = 16; o; o >>= 1) wv += __shfl_xor_sync(0xffffffffu, wv, o);
            if ((t & 31) == 0) red2[t >> 5] = wv;
        }
        __syncthreads();
        if (t == 0) {
            float tot = red2[0] + red2[1] + red2[2] + red2[3];
            out[0] = tot * (1.f / (float)(BATCH * BATCH));
            g_cnt = 0u;  // self-reset for next graph replay
        }
    }
}

// ---------------- launch ----------------------------------------------------
extern "C" void kernel_launch(void* const* d_in, const int* in_sizes, int n_in,
                              void* d_out, int out_size) {
    const float* z = (const float*)d_in[0];
    const float* x = (const float*)d_in[1];
    if (n_in >= 2 && in_sizes[0] == BATCH * NELEM) {  // defensive swap
        const float* tmp = z; z = x; x = tmp;
    }

    int smem_emd  = 2 * 64 * TS * (int)sizeof(float);          // 49664 B
    int smem_zsim = (BATCH * ZS + BATCH) * (int)sizeof(float); // 66560 B
    static int attr_set = 0;
    if (!attr_set) {
        cudaFuncSetAttribute(k_emd,  cudaFuncAttributeMaxDynamicSharedMemorySize, smem_emd);
        cudaFuncSetAttribute(k_zsim, cudaFuncAttributeMaxDynamicSharedMemorySize, smem_zsim);
        attr_set = 1;
    }

    k_zsim<<<BATCH, DIMZ, smem_zsim>>>(z);
    k_sort<<<BATCH, 1024>>>(x);
    dim3 ge(2, 2, NCH);
    k_emd<<<ge, 256, smem_emd>>>();
    k_mse<<<MSEB, 256>>>((float*)d_out);
}

// round 10
// speedup vs baseline: 1.3709x; 1.2218x over previous
#include <cuda_runtime.h>

#define BATCH 128
#define DIMZ  128
#define NELEM 3072
#define MPAD  4096
#define NCHF  128      // emd chunks (one per block)
#define CWF   24       // chunk width: NCHF*CWF == NELEM
#define CS2   132      // emd transposed smem stride (floats; 16B-aligned rows)
#define ZS    129      // zsim smem row stride
#define NB    128

// ---------------- scratch (static device globals; no allocation) -----------
__device__ float g_xs[BATCH * NELEM];          // sorted rows of x
__device__ float g_zcos[BATCH * BATCH];        // cosine similarity matrix
__device__ int   g_maxbits;                    // float-as-int max of zcos (replay-safe)
__device__ float g_part[NCHF * BATCH * BATCH]; // per-chunk EMD partial planes (8MB)
__device__ float g_bsum[NB];                   // per-block mse sums
__device__ unsigned g_cnt;                     // last-block counter (self-resetting)

// ---------------- sort primitives ------------------------------------------
__device__ __forceinline__ void cswap(float& a, float& b, bool asc) {
    float lo = fminf(a, b), hi = fmaxf(a, b);
    a = asc ? lo : hi;
    b = asc ? hi : lo;
}

// In-register bitonic stages j = jstart..1 for outer stage k (4 elems/thread).
__device__ __forceinline__ void reg_sweep(float v[4], int e0, int k, int jstart) {
    bool asc = ((e0 & k) == 0);
    for (int j = jstart; j >= 4; j >>= 1) {
        bool low = ((e0 & j) == 0);
        bool km = (low == asc);
        #pragma unroll
        for (int r = 0; r < 4; r++) {
            float o = __shfl_xor_sync(0xffffffffu, v[r], j >> 2);
            v[r] = km ? fminf(v[r], o) : fmaxf(v[r], o);
        }
    }
    if (jstart >= 2) {
        cswap(v[0], v[2], asc);
        cswap(v[1], v[3], asc);
    }
    {
        bool a0 = ((e0 & k) == 0);
        bool a1 = (((e0 + 2) & k) == 0);
        cswap(v[0], v[1], a0);
        cswap(v[2], v[3], a1);
    }
}

// All smem stages (j = K/2 .. 128) of outer stage K in ONE round trip.
// Thread t (< 4096/M) owns M elements at stride 128: index bits [7..6+log2(M)]
// come from m; direction bit (i & K) lives above them -> uniform per thread.
template<int M, int SH, int K>
__device__ __forceinline__ void merge_group(float* s, int t) {
    if (t < (MPAD / M)) {
        int i0 = (t & 127) | ((t >> 7) << SH);
        float v[M];
        #pragma unroll
        for (int m = 0; m < M; m++) v[m] = s[i0 + (m << 7)];
        bool asc = ((i0 & K) == 0);
        #pragma unroll
        for (int jl = M >> 1; jl; jl >>= 1)
            #pragma unroll
            for (int m = 0; m < M; m++)
                if ((m & jl) == 0) cswap(v[m], v[m ^ jl], asc);
        #pragma unroll
        for (int m = 0; m < M; m++) s[i0 + (m << 7)] = v[m];
    }
}

__device__ __forceinline__ void reload_sweep_store(float* s, float v[4], int e0,
                                                   int k, bool store) {
    float4 f = *reinterpret_cast<const float4*>(&s[e0]);
    v[0] = f.x; v[1] = f.y; v[2] = f.z; v[3] = f.w;
    reg_sweep(v, e0, k, 64);
    if (store) {
        *reinterpret_cast<float4*>(&s[e0]) = make_float4(v[0], v[1], v[2], v[3]);
        __syncthreads();
    }
}

// ---------------- kernel A: zsim + sort (both per-block independent) --------
extern __shared__ float dynsm[];

__global__ __launch_bounds__(1024, 1) void k_zsort(const float* __restrict__ z,
                                                   const float* __restrict__ x) {
    int t = threadIdx.x, b = blockIdx.x;
    __shared__ float redm[4];

    // Early-issue x row load (consumed by sort phase).
    int e0 = t * 4;
    float v[4];
    if (e0 < NELEM) {
        float4 f = *reinterpret_cast<const float4*>(x + b * NELEM + e0);
        v[0] = f.x; v[1] = f.y; v[2] = f.z; v[3] = f.w;
    } else {
        v[0] = v[1] = v[2] = v[3] = __int_as_float(0x7f800000);
    }

    // ---- zsim: norms + cosine row b + global max ----
    {
        float* zs   = dynsm;               // [128][ZS]
        float* sinv = dynsm + BATCH * ZS;  // [128]
        for (int idx = t; idx < BATCH * DIMZ; idx += 1024) {
            int r = idx >> 7, c = idx & 127;
            zs[r * ZS + c] = z[idx];
        }
        __syncthreads();
        if (t < 128) {
            const float* zr = zs + t * ZS;
            float s0 = 0.f, s1 = 0.f, s2 = 0.f, s3 = 0.f;
            #pragma unroll
            for (int kk = 0; kk < DIMZ; kk += 4) {
                float a0 = zr[kk], a1 = zr[kk + 1], a2 = zr[kk + 2], a3 = zr[kk + 3];
                s0 += a0 * a0; s1 += a1 * a1; s2 += a2 * a2; s3 += a3 * a3;
            }
            sinv[t] = 1.f / fmaxf(sqrtf((s0 + s1) + (s2 + s3)), 1e-12f);
        }
        __syncthreads();
        if (t < 128) {
            const float* za = zs + b * ZS;   // broadcast
            const float* zb = zs + t * ZS;   // conflict-free
            float d0 = 0.f, d1 = 0.f, d2 = 0.f, d3 = 0.f;
            #pragma unroll
            for (int kk = 0; kk < DIMZ; kk += 4) {
                d0 += za[kk]     * zb[kk];
                d1 += za[kk + 1] * zb[kk + 1];
                d2 += za[kk + 2] * zb[kk + 2];
                d3 += za[kk + 3] * zb[kk + 3];
            }
            float c = ((d0 + d1) + (d2 + d3)) * sinv[b] * sinv[t];
            g_zcos[b * BATCH + t] = c;
            float m = c;
            #pragma unroll
            for (int o = 16; o; o >>= 1) m = fmaxf(m, __shfl_xor_sync(0xffffffffu, m, o));
            if ((t & 31) == 0) redm[t >> 5] = m;
        }
        __syncthreads();   // all zs reads done; dynsm reusable by sort
        if (t == 0) {
            float mx = fmaxf(fmaxf(redm[0], redm[1]), fmaxf(redm[2], redm[3]));
            atomicMax(&g_maxbits, __float_as_int(mx)); // max >= 1 > 0: int-monotone
        }
    }

    // ---- sort row b (hybrid bitonic, grouped smem stages) ----
    {
        float* s = dynsm;  // [MPAD]

        for (int k = 2; k <= 128; k <<= 1)          // warp-local phase
            reg_sweep(v, e0, k, k >> 1);

        *reinterpret_cast<float4*>(&s[e0]) = make_float4(v[0], v[1], v[2], v[3]);
        __syncthreads();

        // k = 256: single smem stage j = 128, then contiguous reg sweep.
        #pragma unroll
        for (int mm = 0; mm < 2; mm++) {
            int m = t + (mm << 10);
            int i = ((m & ~127) << 1) | (m & 127);
            int li = i | 128;
            bool asc = ((i & 256) == 0);
            float a = s[i], bb = s[li];
            float lo = fminf(a, bb), hi = fmaxf(a, bb);
            s[i]  = asc ? lo : hi;
            s[li] = asc ? hi : lo;
        }
        __syncthreads();
        reload_sweep_store(s, v, e0, 256, true);

        merge_group<4, 9, 512>(s, t);
        __syncthreads();
        reload_sweep_store(s, v, e0, 512, true);

        merge_group<8, 10, 1024>(s, t);
        __syncthreads();
        reload_sweep_store(s, v, e0, 1024, true);

        merge_group<16, 11, 2048>(s, t);
        __syncthreads();
        reload_sweep_store(s, v, e0, 2048, true);

        merge_group<32, 12, 4096>(s, t);
        __syncthreads();
        reload_sweep_store(s, v, e0, 4096, false);

        if (e0 < NELEM)
            *reinterpret_cast<float4*>(g_xs + b * NELEM + e0) =
                make_float4(v[0], v[1], v[2], v[3]);
    }
}

// ---------------- kernel B: EMD plane b (CW=24 split-K) ---------------------
__global__ __launch_bounds__(1024, 1) void k_emd2() {
    __shared__ __align__(16) float st[CWF * CS2];  // transposed: st[c*CS2 + r]
    int t = threadIdx.x, b = blockIdx.x;
    int c0 = b * CWF;
    {
        int r = t >> 3, cb = (t & 7) * 3;
        const float* src = g_xs + r * NELEM + c0 + cb;
        #pragma unroll
        for (int i2 = 0; i2 < 3; i2++) st[(cb + i2) * CS2 + r] = src[i2];
    }
    __syncthreads();

    int w = t >> 5, l = t & 31;
    int txp = (l & 7) | ((w & 3) << 3);    // 0..31
    int typ = (l >> 3) | ((w >> 2) << 2);  // 0..31

    float acc[16];
    #pragma unroll
    for (int q = 0; q < 16; q++) acc[q] = 0.f;

    #pragma unroll
    for (int c = 0; c < CWF; c++) {
        float4 a4 = *reinterpret_cast<const float4*>(st + c * CS2 + 4 * typ);
        float4 b4 = *reinterpret_cast<const float4*>(st + c * CS2 + 4 * txp);
        float a[4] = {a4.x, a4.y, a4.z, a4.w};
        float bb[4] = {b4.x, b4.y, b4.z, b4.w};
        #pragma unroll
        for (int r = 0; r < 4; r++)
            #pragma unroll
            for (int q = 0; q < 4; q++) {
                float d = __fmaf_rn(bb[q], -1.f, a[r]);                     // FFMA-imm
                acc[r * 4 + q] = __fmaf_rn(fabsf(d), 1.f, acc[r * 4 + q]);  // FFMA-imm
            }
    }

    float* outp = g_part + b * (BATCH * BATCH);
    int ri = typ * 4, rj = txp * 4;
    #pragma unroll
    for (int r = 0; r < 4; r++)
        *reinterpret_cast<float4*>(outp + (ri + r) * BATCH + rj) =
            make_float4(acc[r * 4 + 0], acc[r * 4 + 1], acc[r * 4 + 2], acc[r * 4 + 3]);
}

// ---------------- kernel C: combine + MSE + final (last-block) --------------
__global__ __launch_bounds__(1024, 1) void k_mse2(float* __restrict__ out) {
    __shared__ float4 smv[32 * 32];
    __shared__ float r2[4];
    __shared__ bool last;
    int t = threadIdx.x, b = blockIdx.x;
    int w = t >> 5, l = t & 31;
    int I = b * 32 + l;                               // float4 idx in [4096]

    const float4* p4 = reinterpret_cast<const float4*>(g_part);
    float4 s4 = make_float4(0.f, 0.f, 0.f, 0.f);
    #pragma unroll
    for (int q = 0; q < 4; q++) {
        float4 p = p4[(w * 4 + q) * (BATCH * BATCH / 4) + I];
        s4.x += p.x; s4.y += p.y; s4.z += p.z; s4.w += p.w;
    }
    smv[w * 32 + l] = s4;
    __syncthreads();
    if (w < 8) {
        float4 a = smv[w * 32 + l];
        float4 b1 = smv[(w + 8) * 32 + l];
        float4 b2 = smv[(w + 16) * 32 + l];
        float4 b3 = smv[(w + 24) * 32 + l];
        a.x += b1.x + b2.x + b3.x;
        a.y += b1.y + b2.y + b3.y;
        a.z += b1.z + b2.z + b3.z;
        a.w += b1.w + b2.w + b3.w;
        smv[w * 32 + l] = a;
    }
    __syncthreads();
    float vv = 0.f;
    if (w == 0) {
        float4 a = smv[l];
        #pragma unroll
        for (int g = 1; g < 8; g++) {
            float4 p = smv[g * 32 + l];
            a.x += p.x; a.y += p.y; a.z += p.z; a.w += p.w;
        }
        float4 zc = reinterpret_cast<const float4*>(g_zcos)[I];
        float gmax = __int_as_float(g_maxbits);
        const float inv = 1.f / (float)NELEM;
        float dx = a.x * inv + zc.x - gmax;
        float dy = a.y * inv + zc.y - gmax;
        float dz = a.z * inv + zc.z - gmax;
        float dw = a.w * inv + zc.w - gmax;
        vv = dx * dx + dy * dy + dz * dz + dw * dw;
        #pragma unroll
        for (int o = 16; o; o >>= 1) vv += __shfl_xor_sync(0xffffffffu, vv, o);
    }
    if (t == 0) {
        g_bsum[b] = vv;
        __threadfence();
        unsigned c = atomicAdd(&g_cnt, 1u);
        last = (c == (unsigned)(NB - 1));
    }
    __syncthreads();
    if (last) {
        if (t < NB) {
            float wv = g_bsum[t];
            #pragma unroll
            for (int o = 16; o; o >>= 1) wv += __shfl_xor_sync(0xffffffffu, wv, o);
            if ((t & 31) == 0) r2[t >> 5] = wv;
        }
        __syncthreads();
        if (t == 0) {
            out[0] = (r2[0] + r2[1] + r2[2] + r2[3]) * (1.f / (float)(BATCH * BATCH));
            g_cnt = 0u;  // self-reset for next graph replay
        }
    }
}

// ---------------- launch ----------------------------------------------------
extern "C" void kernel_launch(void* const* d_in, const int* in_sizes, int n_in,
                              void* d_out, int out_size) {
    const float* z = (const float*)d_in[0];
    const float* x = (const float*)d_in[1];
    if (n_in >= 2 && in_sizes[0] == BATCH * NELEM) {  // defensive swap
        const float* tmp = z; z = x; x = tmp;
    }

    int smem = (BATCH * ZS + BATCH) * (int)sizeof(float);  // 66560 B
    static int attr_set = 0;
    if (!attr_set) {
        cudaFuncSetAttribute(k_zsort, cudaFuncAttributeMaxDynamicSharedMemorySize, smem);
        attr_set = 1;
    }

    k_zsort<<<NB, 1024, smem>>>(z, x);
    k_emd2<<<NB, 1024>>>();
    k_mse2<<<NB, 1024>>>((float*)d_out);
}